// round 5
// baseline (speedup 1.0000x reference)
#include <cuda_runtime.h>
#include <cstdint>

#define N_ANCH   300000
#define N_CLS    80
#define DET_DIM  85
#define TOPK     1000
#define MAXBOX   300
#define CAP      4096
#define NMS_THR  0.4f

#define GRIDB    148          // <= SM count -> co-resident -> sw grid barrier safe
#define NTHR     1024
#define DYN_BYTES (TOPK * 32 * 4)   // 128000 B: scan mask (sort needs 32K)

// ---------------- device scratch ----------------
__device__ unsigned int       g_scores[N_ANCH];
__device__ unsigned int       g_hist1[65536];   // zeroed by resolve1 phase each run
__device__ unsigned int       g_hist2[256];     // zeroed by block 1 at kernel start
__device__ unsigned int       g_sel_b, g_kth2;
__device__ int                g_cand_cnt;
__device__ unsigned long long g_cand[CAP];
__device__ int                g_topk_idx[TOPK];
__device__ float4             g_boxk[TOPK];
__device__ unsigned int       g_maskmat[TOPK * 32];
__device__ unsigned int       g_bar_count;      // returns to 0 after every barrier
__device__ unsigned int       g_bar_gen;        // monotonic across barriers AND replays

// ---------------- software grid barrier (monotonic generation) ----------------
__device__ __forceinline__ void gbar(unsigned int base, unsigned int k, bool wait) {
    __syncthreads();
    if (threadIdx.x == 0) {
        __threadfence();
        unsigned int a = atomicAdd(&g_bar_count, 1u) + 1u;
        if (a == GRIDB) {
            g_bar_count = 0u;
            __threadfence();
            atomicExch(&g_bar_gen, base + k);
        } else if (wait) {
            while (atomicAdd(&g_bar_gen, 0u) - base < k) __nanosleep(64);
            __threadfence();
        }
    }
    __syncthreads();
}

// ---------------- the single fused kernel ----------------
extern "C" __global__ void __launch_bounds__(NTHR, 1)
nms_fused_kernel(const float* __restrict__ boxes,
                 const float* __restrict__ cls,
                 const float* __restrict__ det,
                 float* __restrict__ out) {
    extern __shared__ unsigned char dynsmem[];
    __shared__ unsigned int suf[1024];
    __shared__ unsigned int win64[64];
    __shared__ int          s_win;
    __shared__ unsigned int h2s[256];
    __shared__ unsigned int sT;
    __shared__ unsigned int keepw[32];
    __shared__ unsigned int wpref[32];
    __shared__ int          s_sel[MAXBOX];
    __shared__ int          s_nkeep;
    __shared__ unsigned int s_base;

    const int t    = threadIdx.x;
    const int blk  = blockIdx.x;
    const int gtid = blk * NTHR + t;

    if (t == 0) s_base = atomicAdd(&g_bar_gen, 0u);
    if (blk == 1) {
        if (t < 256) g_hist2[t] = 0u;
        if (t == 0)  g_cand_cnt = 0;
    }
    __syncthreads();
    const unsigned int base = s_base;

    // ===== Phase 1: per-anchor max over 80 classes (anchor-per-thread, 16-way MLP)
    //       + warp-aggregated 16-bit histogram =====
    {
        for (int a = gtid; a < N_ANCH; a += GRIDB * NTHR) {
            const float4* row = (const float4*)cls + (size_t)a * (N_CLS / 4);
            float4 c0 = row[0], c1 = row[1], c2 = row[2], c3 = row[3];
#pragma unroll
            for (int j = 4; j < N_CLS / 4; j += 4) {
                float4 v0 = row[j], v1 = row[j + 1], v2 = row[j + 2], v3 = row[j + 3];
                c0.x = fmaxf(c0.x, v0.x); c0.y = fmaxf(c0.y, v0.y);
                c0.z = fmaxf(c0.z, v0.z); c0.w = fmaxf(c0.w, v0.w);
                c1.x = fmaxf(c1.x, v1.x); c1.y = fmaxf(c1.y, v1.y);
                c1.z = fmaxf(c1.z, v1.z); c1.w = fmaxf(c1.w, v1.w);
                c2.x = fmaxf(c2.x, v2.x); c2.y = fmaxf(c2.y, v2.y);
                c2.z = fmaxf(c2.z, v2.z); c2.w = fmaxf(c2.w, v2.w);
                c3.x = fmaxf(c3.x, v3.x); c3.y = fmaxf(c3.y, v3.y);
                c3.z = fmaxf(c3.z, v3.z); c3.w = fmaxf(c3.w, v3.w);
            }
            float m = fmaxf(
                fmaxf(fmaxf(fmaxf(c0.x, c0.y), fmaxf(c0.z, c0.w)),
                      fmaxf(fmaxf(c1.x, c1.y), fmaxf(c1.z, c1.w))),
                fmaxf(fmaxf(fmaxf(c2.x, c2.y), fmaxf(c2.z, c2.w)),
                      fmaxf(fmaxf(c3.x, c3.y), fmaxf(c3.z, c3.w))));
            unsigned int k = __float_as_uint(m);   // scores >= 0 -> monotonic bits
            g_scores[a] = k;
            unsigned int bucket = k >> 16;
            unsigned int amask = __activemask();
            unsigned int peers = __match_any_sync(amask, bucket);
            int leader = __ffs(peers) - 1;
            if ((t & 31) == leader) atomicAdd(&g_hist1[bucket], __popc(peers));
        }
    }
    gbar(base, 1, true);

    // ===== Phase 2: resolve 16-bit bucket (block 0) + zero hist1 =====
    if (blk == 0) {
        unsigned int s = 0;
        const uint4* hp = (const uint4*)g_hist1;
#pragma unroll
        for (int i = 0; i < 16; i++) {
            uint4 v = hp[t * 16 + i];
            s += v.x + v.y + v.z + v.w;
        }
        suf[t] = s;
        __syncthreads();
        for (int off = 1; off < 1024; off <<= 1) {
            unsigned int v = suf[t];
            unsigned int u = (t + off < 1024) ? suf[t + off] : 0u;
            __syncthreads();
            suf[t] = v + u;
            __syncthreads();
        }
        unsigned int excl = (t < 1023) ? suf[t + 1] : 0u;
        if (excl < TOPK && suf[t] >= TOPK) s_win = t;
        __syncthreads();
        int w = s_win;
        unsigned int wexcl = (w < 1023) ? suf[w + 1] : 0u;
        if (t < 64) win64[t] = g_hist1[w * 64 + t];
        __syncthreads();
        for (int off = 1; off < 64; off <<= 1) {
            unsigned int v = 0, u = 0;
            if (t < 64) { v = win64[t]; u = (t + off < 64) ? win64[t + off] : 0u; }
            __syncthreads();
            if (t < 64) win64[t] = v + u;
            __syncthreads();
        }
        if (t < 64) {
            unsigned int e = wexcl + ((t < 63) ? win64[t + 1] : 0u);
            unsigned int inc = wexcl + win64[t];
            if (e < TOPK && inc >= TOPK) {
                g_sel_b = (unsigned int)(w * 64 + t);
                g_kth2  = TOPK - e;
            }
        }
        __syncthreads();
        uint4 z = make_uint4(0, 0, 0, 0);
        uint4* hz = (uint4*)g_hist1;
#pragma unroll
        for (int i = 0; i < 16; i++) hz[t * 16 + i] = z;
    }
    gbar(base, 2, true);

    // ===== Phase 3: 8-bit refinement histogram (grid-wide) =====
    {
        unsigned int b = g_sel_b;
        if (gtid < N_ANCH / 4) {
            uint4 k = ((const uint4*)g_scores)[gtid];
            if ((k.x >> 16) == b) atomicAdd(&g_hist2[(k.x >> 8) & 255u], 1u);
            if ((k.y >> 16) == b) atomicAdd(&g_hist2[(k.y >> 8) & 255u], 1u);
            if ((k.z >> 16) == b) atomicAdd(&g_hist2[(k.z >> 8) & 255u], 1u);
            if ((k.w >> 16) == b) atomicAdd(&g_hist2[(k.w >> 8) & 255u], 1u);
        }
    }
    gbar(base, 3, true);

    // ===== Phase 4: per-block redundant resolve2 + grid-wide compact =====
    {
        if (t < 256) h2s[t] = g_hist2[t];
        __syncthreads();
        for (int off = 1; off < 256; off <<= 1) {
            unsigned int v = 0, u = 0;
            if (t < 256) { v = h2s[t]; u = (t + off < 256) ? h2s[t + off] : 0u; }
            __syncthreads();
            if (t < 256) h2s[t] = v + u;
            __syncthreads();
        }
        if (t < 256) {
            unsigned int kth = g_kth2;
            unsigned int e = (t < 255) ? h2s[t + 1] : 0u;
            if (e < kth && h2s[t] >= kth)
                sT = (g_sel_b << 16) | ((unsigned int)t << 8);
        }
        __syncthreads();
        unsigned int T = sT;
        if (gtid < N_ANCH / 4) {
            uint4 k = ((const uint4*)g_scores)[gtid];
            unsigned int bi = (unsigned int)(gtid * 4);
            if (k.x >= T) { int s = atomicAdd(&g_cand_cnt, 1); if (s < CAP) g_cand[s] = ((unsigned long long)k.x << 32) | (0xFFFFFFFFu - bi); }
            if (k.y >= T) { int s = atomicAdd(&g_cand_cnt, 1); if (s < CAP) g_cand[s] = ((unsigned long long)k.y << 32) | (0xFFFFFFFFu - (bi + 1)); }
            if (k.z >= T) { int s = atomicAdd(&g_cand_cnt, 1); if (s < CAP) g_cand[s] = ((unsigned long long)k.z << 32) | (0xFFFFFFFFu - (bi + 2)); }
            if (k.w >= T) { int s = atomicAdd(&g_cand_cnt, 1); if (s < CAP) g_cand[s] = ((unsigned long long)k.w << 32) | (0xFFFFFFFFu - (bi + 3)); }
        }
    }
    gbar(base, 4, true);

    // ===== Phase 5: bitonic sort of candidates + box gather (block 0) =====
    if (blk == 0) {
        unsigned long long* scand = (unsigned long long*)dynsmem;
        int cnt = g_cand_cnt;
        if (cnt > CAP) cnt = CAP;
        int S = (cnt <= 2048) ? 2048 : CAP;
        for (int i = t; i < S; i += NTHR)
            scand[i] = (i < cnt) ? g_cand[i] : 0ull;
        __syncthreads();
        for (int k = 2; k <= S; k <<= 1) {
            for (int j = k >> 1; j > 0; j >>= 1) {
                for (int idx = t; idx < S; idx += NTHR) {
                    int l = idx ^ j;
                    if (l > idx) {
                        bool up = ((idx & k) == 0);
                        unsigned long long a = scand[idx], b = scand[l];
                        bool sw = up ? (a < b) : (a > b);
                        if (sw) { scand[idx] = b; scand[l] = a; }
                    }
                }
                __syncthreads();
            }
        }
        if (t < TOPK) {
            unsigned long long key = scand[t];
            int idx = (int)(0xFFFFFFFFu - (unsigned int)key);
            g_topk_idx[t] = idx;
            g_boxk[t] = ((const float4*)boxes)[idx];
        }
    }
    gbar(base, 5, true);

    // ===== Phase 6: IoU > thr bitmask (grid-wide, bit-exact fp32) =====
    {
        int w = gtid;
        if (w < TOPK * 32) {
            int i = w >> 5, wj = w & 31;
            float4 bi = g_boxk[i];
            float ai = __fmul_rn(__fsub_rn(bi.z, bi.x), __fsub_rn(bi.w, bi.y));
            unsigned int bits = 0u;
            int j0 = wj * 32;
#pragma unroll 8
            for (int tt = 0; tt < 32; tt++) {
                int j = j0 + tt;
                if (j < TOPK) {
                    float4 bj = g_boxk[j];
                    float aj = __fmul_rn(__fsub_rn(bj.z, bj.x), __fsub_rn(bj.w, bj.y));
                    float ih = fmaxf(__fsub_rn(fminf(bi.z, bj.z), fmaxf(bi.x, bj.x)), 0.0f);
                    float iw = fmaxf(__fsub_rn(fminf(bi.w, bj.w), fmaxf(bi.y, bj.y)), 0.0f);
                    float inter = __fmul_rn(ih, iw);
                    float denom = __fadd_rn(__fsub_rn(__fadd_rn(ai, aj), inter), 1e-8f);
                    float iou = __fdiv_rn(inter, denom);
                    if (iou > NMS_THR) bits |= (1u << tt);
                }
            }
            g_maskmat[w] = bits;
        }
    }
    gbar(base, 6, blk == 0);
    if (blk != 0) return;

    // ===== Phase 7: sequential greedy keep-scan + output gather (block 0) =====
    {
        unsigned int* smask = (unsigned int*)dynsmem;   // TOPK*32 words
        for (int i = t; i < TOPK * 32; i += NTHR) smask[i] = g_maskmat[i];
        __syncthreads();

        if (t < 32) {
            unsigned int kw = 0u;
            unsigned int m = smask[t];
            for (int i = 0; i < TOPK; i++) {
                unsigned int mn = (i + 1 < TOPK) ? smask[(i + 1) * 32 + t] : 0u;
                int any = __any_sync(0xFFFFFFFFu, (kw & m) != 0u);
                if (!any && t == (i >> 5)) kw |= 1u << (i & 31);
                m = mn;
            }
            keepw[t] = kw;
            unsigned int pc = __popc(kw);
            unsigned int inc = pc;
            for (int off = 1; off < 32; off <<= 1) {
                unsigned int v = __shfl_up_sync(0xFFFFFFFFu, inc, off);
                if (t >= off) inc += v;
            }
            wpref[t] = inc - pc;
            if (t == 31) s_nkeep = (int)inc;
        }
        __syncthreads();

        if (t < TOPK) {
            int w = t >> 5, b = t & 31;
            unsigned int kw = keepw[w];
            if ((kw >> b) & 1u) {
                int rank = (int)wpref[w] + __popc(kw & ((1u << b) - 1u));
                if (rank < MAXBOX) s_sel[rank] = g_topk_idx[t];
            }
        }
        __syncthreads();

        int nk = s_nkeep;
        if (nk > MAXBOX) nk = MAXBOX;
        for (int e = t; e < MAXBOX * DET_DIM; e += NTHR) {
            int r = e / DET_DIM;
            int c = e - r * DET_DIM;
            out[e] = (r < nk) ? det[(size_t)s_sel[r] * DET_DIM + c] : 0.0f;
        }
    }
}

// ---------------- launch: ONE kernel ----------------
extern "C" void kernel_launch(void* const* d_in, const int* in_sizes, int n_in,
                              void* d_out, int out_size) {
    const float* boxes = (const float*)d_in[0];
    const float* cls   = (const float*)d_in[1];
    const float* det   = (const float*)d_in[2];
    float* out = (float*)d_out;

    cudaFuncSetAttribute((const void*)nms_fused_kernel,
                         cudaFuncAttributeMaxDynamicSharedMemorySize, DYN_BYTES);

    nms_fused_kernel<<<GRIDB, NTHR, DYN_BYTES>>>(boxes, cls, det, out);
}

// round 6
// speedup vs baseline: 1.4633x; 1.4633x over previous
#include <cuda_runtime.h>
#include <cstdint>

#define N_ANCH   300000
#define N_CLS    80
#define DET_DIM  85
#define TOPK     1000
#define MAXBOX   300
#define CAP      4096
#define NMS_THR  0.4f

#define GRIDB    148
#define NTHR     1024
#define DYN_BYTES (TOPK * 32 * 4)   // 128000 B (scan mask; sort uses 32KB)

// ---------------- device scratch ----------------
__device__ unsigned int       g_scores[N_ANCH];
__device__ unsigned int       g_histA[256];   // bits[31:24]; zeroed by blk1 in P5
__device__ unsigned int       g_histB[256];   // bits[23:16]
__device__ unsigned int       g_histC[256];   // bits[15:8]
__device__ int                g_cand_cnt;     // reset by blk0 in P5
__device__ unsigned long long g_cand[CAP];
__device__ int                g_topk_idx[TOPK];
__device__ float4             g_boxk[TOPK];
__device__ unsigned int       g_maskmat[TOPK * 32];
__device__ unsigned int       g_bar_count;
__device__ unsigned int       g_bar_gen;      // monotonic across barriers AND replays

// ---------------- grid barrier: load-polling, monotonic generation ----------------
__device__ __forceinline__ void gbar(unsigned int base, unsigned int k, bool wait) {
    __syncthreads();
    if (threadIdx.x == 0) {
        __threadfence();
        unsigned int a = atomicAdd(&g_bar_count, 1u) + 1u;
        if (a == GRIDB) {
            g_bar_count = 0u;
            __threadfence();
            atomicExch(&g_bar_gen, base + k);
        } else if (wait) {
            const volatile unsigned int* vg = &g_bar_gen;
            while (*vg - base < k) __nanosleep(64);
            __threadfence();
        }
    }
    __syncthreads();
}

// warp-aggregated shared-memory histogram increment
__device__ __forceinline__ void aggInc(unsigned int* sh, unsigned int bucket) {
    unsigned int am = __activemask();
    unsigned int peers = __match_any_sync(am, bucket);
    int leader = __ffs(peers) - 1;
    if ((threadIdx.x & 31) == leader) atomicAdd(&sh[bucket], __popc(peers));
}

// warp-aggregated candidate emission
__device__ __forceinline__ void emit(unsigned int key, unsigned int idx, unsigned int T) {
    bool p = (key >= T);
    unsigned int am = __activemask();
    unsigned int bal = __ballot_sync(am, p);
    if (p) {
        int lane = threadIdx.x & 31;
        int leader = __ffs(bal) - 1;
        int base = 0;
        if (lane == leader) base = atomicAdd(&g_cand_cnt, __popc(bal));
        base = __shfl_sync(bal, base, leader);
        int slot = base + __popc(bal & ((1u << lane) - 1u));
        if (slot < CAP)
            g_cand[slot] = ((unsigned long long)key << 32) |
                           (unsigned long long)(0xFFFFFFFFu - idx);
    }
}

// redundant per-block resolve of one 8-bit digit from a global 256-bin histogram
__device__ __forceinline__ void resolve256(const unsigned int* gh, unsigned int kth,
                                           unsigned int* shR,
                                           unsigned int* s_dig, unsigned int* s_kth) {
    int t = threadIdx.x;
    if (t < 256) shR[t] = gh[t];
    __syncthreads();
    for (int off = 1; off < 256; off <<= 1) {   // inclusive suffix scan
        unsigned int v = 0, u = 0;
        if (t < 256) { v = shR[t]; u = (t + off < 256) ? shR[t + off] : 0u; }
        __syncthreads();
        if (t < 256) shR[t] = v + u;
        __syncthreads();
    }
    if (t < 256) {
        unsigned int e = (t < 255) ? shR[t + 1] : 0u;
        if (e < kth && shR[t] >= kth) { *s_dig = (unsigned int)t; *s_kth = kth - e; }
    }
    __syncthreads();
}

// ---------------- the single fused kernel ----------------
extern "C" __global__ void __launch_bounds__(NTHR, 1)
nms_fused_kernel(const float* __restrict__ boxes,
                 const float* __restrict__ cls,
                 const float* __restrict__ det,
                 float* __restrict__ out) {
    extern __shared__ unsigned char dynsmem[];
    __shared__ unsigned int shH[256];     // histogram accumulation
    __shared__ unsigned int shR[256];     // resolve scratch
    __shared__ unsigned int s_d1, s_k1, s_d2, s_k2, s_d3;
    __shared__ unsigned int keepw[32], wpref[32];
    __shared__ int  s_sel[MAXBOX];
    __shared__ int  s_nkeep;
    __shared__ unsigned int s_base;

    const int t    = threadIdx.x;
    const int blk  = blockIdx.x;
    const int gtid = blk * NTHR + t;

    if (t == 0) s_base = atomicAdd(&g_bar_gen, 0u);
    if (t < 256) shH[t] = 0u;
    __syncthreads();
    const unsigned int base = s_base;

    // ===== P1: per-anchor max over 80 classes + smem hist on bits[31:24] =====
    for (int a = gtid; a < N_ANCH; a += GRIDB * NTHR) {
        const float4* row = (const float4*)cls + (size_t)a * (N_CLS / 4);
        float4 c0 = row[0], c1 = row[1], c2 = row[2], c3 = row[3];
#pragma unroll
        for (int j = 4; j < N_CLS / 4; j += 4) {
            float4 v0 = row[j], v1 = row[j + 1], v2 = row[j + 2], v3 = row[j + 3];
            c0.x = fmaxf(c0.x, v0.x); c0.y = fmaxf(c0.y, v0.y);
            c0.z = fmaxf(c0.z, v0.z); c0.w = fmaxf(c0.w, v0.w);
            c1.x = fmaxf(c1.x, v1.x); c1.y = fmaxf(c1.y, v1.y);
            c1.z = fmaxf(c1.z, v1.z); c1.w = fmaxf(c1.w, v1.w);
            c2.x = fmaxf(c2.x, v2.x); c2.y = fmaxf(c2.y, v2.y);
            c2.z = fmaxf(c2.z, v2.z); c2.w = fmaxf(c2.w, v2.w);
            c3.x = fmaxf(c3.x, v3.x); c3.y = fmaxf(c3.y, v3.y);
            c3.z = fmaxf(c3.z, v3.z); c3.w = fmaxf(c3.w, v3.w);
        }
        float m = fmaxf(
            fmaxf(fmaxf(fmaxf(c0.x, c0.y), fmaxf(c0.z, c0.w)),
                  fmaxf(fmaxf(c1.x, c1.y), fmaxf(c1.z, c1.w))),
            fmaxf(fmaxf(fmaxf(c2.x, c2.y), fmaxf(c2.z, c2.w)),
                  fmaxf(fmaxf(c3.x, c3.y), fmaxf(c3.z, c3.w))));
        unsigned int k = __float_as_uint(m);     // scores >= 0 -> monotonic bits
        g_scores[a] = k;
        aggInc(shH, k >> 24);
    }
    __syncthreads();
    if (t < 256 && shH[t]) atomicAdd(&g_histA[t], shH[t]);
    gbar(base, 1, true);

    // ===== P2: resolve digit 1 (redundant per block) + hist bits[23:16] =====
    resolve256(g_histA, TOPK, shR, &s_d1, &s_k1);
    if (t < 256) shH[t] = 0u;
    __syncthreads();
    {
        unsigned int d1 = s_d1;
        if (gtid < N_ANCH / 4) {
            uint4 k = ((const uint4*)g_scores)[gtid];
            if ((k.x >> 24) == d1) aggInc(shH, (k.x >> 16) & 255u);
            if ((k.y >> 24) == d1) aggInc(shH, (k.y >> 16) & 255u);
            if ((k.z >> 24) == d1) aggInc(shH, (k.z >> 16) & 255u);
            if ((k.w >> 24) == d1) aggInc(shH, (k.w >> 16) & 255u);
        }
    }
    __syncthreads();
    if (t < 256 && shH[t]) atomicAdd(&g_histB[t], shH[t]);
    gbar(base, 2, true);

    // ===== P3: resolve digit 2 + hist bits[15:8] =====
    resolve256(g_histB, s_k1, shR, &s_d2, &s_k2);
    if (t < 256) shH[t] = 0u;
    __syncthreads();
    {
        unsigned int pre16 = (s_d1 << 8) | s_d2;
        if (gtid < N_ANCH / 4) {
            uint4 k = ((const uint4*)g_scores)[gtid];
            if ((k.x >> 16) == pre16) aggInc(shH, (k.x >> 8) & 255u);
            if ((k.y >> 16) == pre16) aggInc(shH, (k.y >> 8) & 255u);
            if ((k.z >> 16) == pre16) aggInc(shH, (k.z >> 8) & 255u);
            if ((k.w >> 16) == pre16) aggInc(shH, (k.w >> 8) & 255u);
        }
    }
    __syncthreads();
    if (t < 256 && shH[t]) atomicAdd(&g_histC[t], shH[t]);
    gbar(base, 3, true);

    // ===== P4: resolve digit 3 -> threshold T; warp-aggregated compact =====
    resolve256(g_histC, s_k2, shR, &s_d3, &s_k1 /*unused*/);
    {
        unsigned int T = (s_d1 << 24) | (s_d2 << 16) | (s_d3 << 8);
        if (gtid < N_ANCH / 4) {
            uint4 k = ((const uint4*)g_scores)[gtid];
            unsigned int bi = (unsigned int)(gtid * 4);
            emit(k.x, bi, T);
            emit(k.y, bi + 1, T);
            emit(k.z, bi + 2, T);
            emit(k.w, bi + 3, T);
        }
    }
    gbar(base, 4, true);

    // ===== P5: block0 sorts candidates + gathers boxes; block1 zeroes hists =====
    if (blk == 1) {
        if (t < 256) { g_histA[t] = 0u; g_histB[t] = 0u; g_histC[t] = 0u; }
    }
    if (blk == 0) {
        unsigned long long* scand = (unsigned long long*)dynsmem;
        int cnt = g_cand_cnt;
        __syncthreads();
        if (t == 0) g_cand_cnt = 0;
        if (cnt > CAP) cnt = CAP;
        int S = (cnt <= 2048) ? 2048 : CAP;
        for (int i = t; i < S; i += NTHR)
            scand[i] = (i < cnt) ? g_cand[i] : 0ull;
        __syncthreads();
        for (int k = 2; k <= S; k <<= 1) {
            for (int j = k >> 1; j > 0; j >>= 1) {
                for (int idx = t; idx < S; idx += NTHR) {
                    int l = idx ^ j;
                    if (l > idx) {
                        bool up = ((idx & k) == 0);
                        unsigned long long a = scand[idx], b = scand[l];
                        bool sw = up ? (a < b) : (a > b);
                        if (sw) { scand[idx] = b; scand[l] = a; }
                    }
                }
                __syncthreads();
            }
        }
        if (t < TOPK) {
            unsigned long long key = scand[t];
            int idx = (int)(0xFFFFFFFFu - (unsigned int)key);
            g_topk_idx[t] = idx;
            g_boxk[t] = ((const float4*)boxes)[idx];
        }
    }
    gbar(base, 5, true);

    // ===== P6: IoU > thr bitmask (grid-wide, bit-exact fp32) =====
    if (gtid < TOPK * 32) {
        int i = gtid >> 5, wj = gtid & 31;
        float4 bi = g_boxk[i];
        float ai = __fmul_rn(__fsub_rn(bi.z, bi.x), __fsub_rn(bi.w, bi.y));
        unsigned int bits = 0u;
        int j0 = wj * 32;
#pragma unroll 8
        for (int tt = 0; tt < 32; tt++) {
            int j = j0 + tt;
            if (j < TOPK) {
                float4 bj = g_boxk[j];
                float aj = __fmul_rn(__fsub_rn(bj.z, bj.x), __fsub_rn(bj.w, bj.y));
                float ih = fmaxf(__fsub_rn(fminf(bi.z, bj.z), fmaxf(bi.x, bj.x)), 0.0f);
                float iw = fmaxf(__fsub_rn(fminf(bi.w, bj.w), fmaxf(bi.y, bj.y)), 0.0f);
                float inter = __fmul_rn(ih, iw);
                float denom = __fadd_rn(__fsub_rn(__fadd_rn(ai, aj), inter), 1e-8f);
                float iou = __fdiv_rn(inter, denom);
                if (iou > NMS_THR) bits |= (1u << tt);
            }
        }
        g_maskmat[gtid] = bits;
    }
    gbar(base, 6, blk == 0);
    if (blk != 0) return;

    // ===== P7: block0 sequential greedy keep-scan + output gather =====
    {
        unsigned int* smask = (unsigned int*)dynsmem;   // TOPK*32 words
        for (int i = t; i < TOPK * 32; i += NTHR) smask[i] = g_maskmat[i];
        __syncthreads();

        if (t < 32) {
            unsigned int kw = 0u;
            unsigned int m = smask[t];
            for (int i = 0; i < TOPK; i++) {
                unsigned int mn = (i + 1 < TOPK) ? smask[(i + 1) * 32 + t] : 0u;
                int any = __any_sync(0xFFFFFFFFu, (kw & m) != 0u);
                if (!any && t == (i >> 5)) kw |= 1u << (i & 31);
                m = mn;
            }
            keepw[t] = kw;
            unsigned int pc = __popc(kw);
            unsigned int inc = pc;
            for (int off = 1; off < 32; off <<= 1) {
                unsigned int v = __shfl_up_sync(0xFFFFFFFFu, inc, off);
                if (t >= off) inc += v;
            }
            wpref[t] = inc - pc;
            if (t == 31) s_nkeep = (int)inc;
        }
        __syncthreads();

        if (t < TOPK) {
            int w = t >> 5, b = t & 31;
            unsigned int kw = keepw[w];
            if ((kw >> b) & 1u) {
                int rank = (int)wpref[w] + __popc(kw & ((1u << b) - 1u));
                if (rank < MAXBOX) s_sel[rank] = g_topk_idx[t];
            }
        }
        __syncthreads();

        int nk = s_nkeep;
        if (nk > MAXBOX) nk = MAXBOX;
        for (int e = t; e < MAXBOX * DET_DIM; e += NTHR) {
            int r = e / DET_DIM;
            int c = e - r * DET_DIM;
            out[e] = (r < nk) ? det[(size_t)s_sel[r] * DET_DIM + c] : 0.0f;
        }
    }
}

// ---------------- launch: ONE kernel ----------------
extern "C" void kernel_launch(void* const* d_in, const int* in_sizes, int n_in,
                              void* d_out, int out_size) {
    const float* boxes = (const float*)d_in[0];
    const float* cls   = (const float*)d_in[1];
    const float* det   = (const float*)d_in[2];
    float* out = (float*)d_out;

    cudaFuncSetAttribute((const void*)nms_fused_kernel,
                         cudaFuncAttributeMaxDynamicSharedMemorySize, DYN_BYTES);

    nms_fused_kernel<<<GRIDB, NTHR, DYN_BYTES>>>(boxes, cls, det, out);
}

// round 7
// speedup vs baseline: 1.7429x; 1.1911x over previous
#include <cuda_runtime.h>
#include <cstdint>

#define N_ANCH   300000
#define N_CLS    80
#define DET_DIM  85
#define TOPK     1000
#define MAXBOX   300
#define CAP      4096
#define NMS_THR  0.4f

#define GRIDB    148
#define NTHR     1024
#define NWARPS   (GRIDB * (NTHR / 32))     // 4736
#define NCHUNK   (N_ANCH / 32)             // 9375 (exact)
#define DYN_BYTES (TOPK * 32 * 4)          // 128000 B (P1 stage 80K, P5 sort 32K, P7 mask 125K)

// ---------------- device scratch ----------------
__device__ unsigned int       g_scores[N_ANCH];
__device__ unsigned int       g_histA[256];
__device__ unsigned int       g_histB[256];
__device__ unsigned int       g_histC[256];
__device__ int                g_cand_cnt;
__device__ unsigned long long g_cand[CAP];
__device__ int                g_topk_idx[TOPK];
__device__ float4             g_boxk[TOPK];
__device__ unsigned int       g_maskmat[32 * TOPK];   // TRANSPOSED: [colword][row]
__device__ unsigned int       g_bar_count;
__device__ unsigned int       g_bar_gen;

// ---------------- grid barrier ----------------
__device__ __forceinline__ void gbar(unsigned int base, unsigned int k, bool wait) {
    __syncthreads();
    if (threadIdx.x == 0) {
        __threadfence();
        unsigned int a = atomicAdd(&g_bar_count, 1u) + 1u;
        if (a == GRIDB) {
            g_bar_count = 0u;
            __threadfence();
            atomicExch(&g_bar_gen, base + k);
        } else if (wait) {
            const volatile unsigned int* vg = &g_bar_gen;
            while (*vg - base < k) __nanosleep(64);
            __threadfence();
        }
    }
    __syncthreads();
}

__device__ __forceinline__ void aggInc(unsigned int* sh, unsigned int bucket) {
    unsigned int am = __activemask();
    unsigned int peers = __match_any_sync(am, bucket);
    int leader = __ffs(peers) - 1;
    if ((threadIdx.x & 31) == leader) atomicAdd(&sh[bucket], __popc(peers));
}

__device__ __forceinline__ void emit(unsigned int key, unsigned int idx, unsigned int T) {
    bool p = (key >= T);
    unsigned int am = __activemask();
    unsigned int bal = __ballot_sync(am, p);
    if (p) {
        int lane = threadIdx.x & 31;
        int leader = __ffs(bal) - 1;
        int base = 0;
        if (lane == leader) base = atomicAdd(&g_cand_cnt, __popc(bal));
        base = __shfl_sync(bal, base, leader);
        int slot = base + __popc(bal & ((1u << lane) - 1u));
        if (slot < CAP)
            g_cand[slot] = ((unsigned long long)key << 32) |
                           (unsigned long long)(0xFFFFFFFFu - idx);
    }
}

__device__ __forceinline__ void resolve256(const unsigned int* gh, unsigned int kth,
                                           unsigned int* shR,
                                           unsigned int* s_dig, unsigned int* s_kth) {
    int t = threadIdx.x;
    if (t < 256) shR[t] = gh[t];
    __syncthreads();
    for (int off = 1; off < 256; off <<= 1) {
        unsigned int v = 0, u = 0;
        if (t < 256) { v = shR[t]; u = (t + off < 256) ? shR[t + off] : 0u; }
        __syncthreads();
        if (t < 256) shR[t] = v + u;
        __syncthreads();
    }
    if (t < 256) {
        unsigned int e = (t < 255) ? shR[t + 1] : 0u;
        if (e < kth && shR[t] >= kth) { *s_dig = (unsigned int)t; *s_kth = kth - e; }
    }
    __syncthreads();
}

// ---------------- the single fused kernel ----------------
extern "C" __global__ void __launch_bounds__(NTHR, 1)
nms_fused_kernel(const float* __restrict__ boxes,
                 const float* __restrict__ cls,
                 const float* __restrict__ det,
                 float* __restrict__ out) {
    extern __shared__ unsigned char dynsmem[];
    __shared__ unsigned int shH[256];
    __shared__ unsigned int shR[256];
    __shared__ unsigned int s_d1, s_k1, s_d2, s_k2, s_d3;
    __shared__ unsigned int keepw[32], wpref[32];
    __shared__ int  s_sel[MAXBOX];
    __shared__ int  s_nkeep;
    __shared__ unsigned int s_base;

    const int t    = threadIdx.x;
    const int blk  = blockIdx.x;
    const int gtid = blk * NTHR + t;
    const int lane = t & 31;
    const int warp = t >> 5;

    if (t == 0) s_base = atomicAdd(&g_bar_gen, 0u);
    if (t < 256) shH[t] = 0u;
    __syncthreads();
    const unsigned int base = s_base;

    // ===== P1: warp-cooperative coalesced per-anchor max + smem hist[31:24] =====
    {
        float* ws = (float*)dynsmem + warp * 640;   // 32 warps * 640 floats = 80KB
        int gwarp = blk * 32 + warp;
        for (int chunk = gwarp; chunk < NCHUNK; chunk += NWARPS) {
            int A0 = chunk * 32;
            const float4* gp = (const float4*)cls + (size_t)A0 * (N_CLS / 4);
#pragma unroll
            for (int s = 0; s < 20; s++) {
                float4 v = gp[s * 32 + lane];       // fully coalesced
                ws[s * 32 + lane] = fmaxf(fmaxf(v.x, v.y), fmaxf(v.z, v.w));
            }
            __syncwarp();
            float mm = ws[lane * 20];
#pragma unroll
            for (int c = 1; c < 20; c++) mm = fmaxf(mm, ws[lane * 20 + c]);
            __syncwarp();
            unsigned int k = __float_as_uint(mm);   // scores >= 0 -> monotonic bits
            g_scores[A0 + lane] = k;
            aggInc(shH, k >> 24);
        }
    }
    __syncthreads();
    if (t < 256 && shH[t]) atomicAdd(&g_histA[t], shH[t]);
    gbar(base, 1, true);

    // ===== P2: resolve digit 1 + hist bits[23:16] =====
    resolve256(g_histA, TOPK, shR, &s_d1, &s_k1);
    if (t < 256) shH[t] = 0u;
    __syncthreads();
    {
        unsigned int d1 = s_d1;
        if (gtid < N_ANCH / 4) {
            uint4 k = ((const uint4*)g_scores)[gtid];
            if ((k.x >> 24) == d1) aggInc(shH, (k.x >> 16) & 255u);
            if ((k.y >> 24) == d1) aggInc(shH, (k.y >> 16) & 255u);
            if ((k.z >> 24) == d1) aggInc(shH, (k.z >> 16) & 255u);
            if ((k.w >> 24) == d1) aggInc(shH, (k.w >> 16) & 255u);
        }
    }
    __syncthreads();
    if (t < 256 && shH[t]) atomicAdd(&g_histB[t], shH[t]);
    gbar(base, 2, true);

    // ===== P3: resolve digit 2 + hist bits[15:8] =====
    resolve256(g_histB, s_k1, shR, &s_d2, &s_k2);
    if (t < 256) shH[t] = 0u;
    __syncthreads();
    {
        unsigned int pre16 = (s_d1 << 8) | s_d2;
        if (gtid < N_ANCH / 4) {
            uint4 k = ((const uint4*)g_scores)[gtid];
            if ((k.x >> 16) == pre16) aggInc(shH, (k.x >> 8) & 255u);
            if ((k.y >> 16) == pre16) aggInc(shH, (k.y >> 8) & 255u);
            if ((k.z >> 16) == pre16) aggInc(shH, (k.z >> 8) & 255u);
            if ((k.w >> 16) == pre16) aggInc(shH, (k.w >> 8) & 255u);
        }
    }
    __syncthreads();
    if (t < 256 && shH[t]) atomicAdd(&g_histC[t], shH[t]);
    gbar(base, 3, true);

    // ===== P4: resolve digit 3 -> threshold; warp-aggregated compact =====
    resolve256(g_histC, s_k2, shR, &s_d3, &s_k1 /*unused*/);
    {
        unsigned int T = (s_d1 << 24) | (s_d2 << 16) | (s_d3 << 8);
        if (gtid < N_ANCH / 4) {
            uint4 k = ((const uint4*)g_scores)[gtid];
            unsigned int bi = (unsigned int)(gtid * 4);
            emit(k.x, bi, T);
            emit(k.y, bi + 1, T);
            emit(k.z, bi + 2, T);
            emit(k.w, bi + 3, T);
        }
    }
    gbar(base, 4, true);

    // ===== P5: block0 sorts candidates + gathers boxes; block1 zeroes hists =====
    if (blk == 1) {
        if (t < 256) { g_histA[t] = 0u; g_histB[t] = 0u; g_histC[t] = 0u; }
    }
    if (blk == 0) {
        unsigned long long* scand = (unsigned long long*)dynsmem;
        int cnt = g_cand_cnt;
        __syncthreads();
        if (t == 0) g_cand_cnt = 0;
        if (cnt > CAP) cnt = CAP;
        int S = (cnt <= 2048) ? 2048 : CAP;
        for (int i = t; i < S; i += NTHR)
            scand[i] = (i < cnt) ? g_cand[i] : 0ull;
        __syncthreads();
        for (int k = 2; k <= S; k <<= 1) {
            for (int j = k >> 1; j > 0; j >>= 1) {
                for (int idx = t; idx < S; idx += NTHR) {
                    int l = idx ^ j;
                    if (l > idx) {
                        bool up = ((idx & k) == 0);
                        unsigned long long a = scand[idx], b = scand[l];
                        bool sw = up ? (a < b) : (a > b);
                        if (sw) { scand[idx] = b; scand[l] = a; }
                    }
                }
                __syncthreads();
            }
        }
        if (t < TOPK) {
            unsigned long long key = scand[t];
            int idx = (int)(0xFFFFFFFFu - (unsigned int)key);
            g_topk_idx[t] = idx;
            g_boxk[t] = ((const float4*)boxes)[idx];
        }
    }
    gbar(base, 5, true);

    // ===== P6: IoU bitmask, TRANSPOSED layout [colword][row] (bit-exact fp32) =====
    if (gtid < 32 * TOPK) {
        int wj = gtid / TOPK;            // column word
        int i  = gtid - wj * TOPK;       // row
        float4 bi = g_boxk[i];
        float ai = __fmul_rn(__fsub_rn(bi.z, bi.x), __fsub_rn(bi.w, bi.y));
        unsigned int bits = 0u;
        int j0 = wj * 32;
#pragma unroll 8
        for (int tt = 0; tt < 32; tt++) {
            int j = j0 + tt;
            if (j < TOPK) {
                float4 bj = g_boxk[j];
                float aj = __fmul_rn(__fsub_rn(bj.z, bj.x), __fsub_rn(bj.w, bj.y));
                float ih = fmaxf(__fsub_rn(fminf(bi.z, bj.z), fmaxf(bi.x, bj.x)), 0.0f);
                float iw = fmaxf(__fsub_rn(fminf(bi.w, bj.w), fmaxf(bi.y, bj.y)), 0.0f);
                float inter = __fmul_rn(ih, iw);
                float denom = __fadd_rn(__fsub_rn(__fadd_rn(ai, aj), inter), 1e-8f);
                float iou = __fdiv_rn(inter, denom);
                if (iou > NMS_THR) bits |= (1u << tt);
            }
        }
        g_maskmat[gtid] = bits;          // coalesced
    }
    gbar(base, 6, blk == 0);
    if (blk != 0) return;

    // ===== P7: block0 tiled greedy keep-scan (registers) + output gather =====
    {
        unsigned int* smask = (unsigned int*)dynsmem;   // [w*TOPK + r], 32000 words
        for (int i = t; i < 32 * TOPK; i += NTHR) smask[i] = g_maskmat[i];
        __syncthreads();

        if (t < 32) {   // warp 0
            for (int tile = 0; tile < 32; tile++) {
                int r = tile * 32 + lane;
                int nrows = TOPK - tile * 32; if (nrows > 32) nrows = 32;
                // parallel: suppressed by any kept box in prior complete words
                bool base_i = false;
                unsigned int wt_i = 0u;
                if (r < TOPK) {
                    for (int w = 0; w < tile; w++)
                        base_i |= (keepw[w] & smask[w * TOPK + r]) != 0u;
                    wt_i = smask[tile * TOPK + r];   // diagonal word
                }
                unsigned int bases = __ballot_sync(0xFFFFFFFFu, base_i);
                unsigned int keep_tile = 0u;
#pragma unroll
                for (int rr = 0; rr < 32; rr++) {
                    unsigned int word_r = __shfl_sync(0xFFFFFFFFu, wt_i, rr);
                    bool sup = ((bases >> rr) & 1u) ||
                               ((keep_tile & word_r & ((1u << rr) - 1u)) != 0u);
                    if (!sup && rr < nrows) keep_tile |= 1u << rr;
                }
                if (lane == 0) keepw[tile] = keep_tile;
                __syncwarp();
            }
            // prefix over keep counts
            unsigned int kw = keepw[lane];
            unsigned int pc = __popc(kw);
            unsigned int inc = pc;
            for (int off = 1; off < 32; off <<= 1) {
                unsigned int v = __shfl_up_sync(0xFFFFFFFFu, inc, off);
                if (lane >= off) inc += v;
            }
            wpref[lane] = inc - pc;
            if (lane == 31) s_nkeep = (int)inc;
        }
        __syncthreads();

        if (t < TOPK) {
            int w = t >> 5, b = t & 31;
            unsigned int kw = keepw[w];
            if ((kw >> b) & 1u) {
                int rank = (int)wpref[w] + __popc(kw & ((1u << b) - 1u));
                if (rank < MAXBOX) s_sel[rank] = g_topk_idx[t];
            }
        }
        __syncthreads();

        int nk = s_nkeep;
        if (nk > MAXBOX) nk = MAXBOX;
        for (int e = t; e < MAXBOX * DET_DIM; e += NTHR) {
            int r = e / DET_DIM;
            int c = e - r * DET_DIM;
            out[e] = (r < nk) ? det[(size_t)s_sel[r] * DET_DIM + c] : 0.0f;
        }
    }
}

// ---------------- launch: ONE kernel ----------------
extern "C" void kernel_launch(void* const* d_in, const int* in_sizes, int n_in,
                              void* d_out, int out_size) {
    const float* boxes = (const float*)d_in[0];
    const float* cls   = (const float*)d_in[1];
    const float* det   = (const float*)d_in[2];
    float* out = (float*)d_out;

    cudaFuncSetAttribute((const void*)nms_fused_kernel,
                         cudaFuncAttributeMaxDynamicSharedMemorySize, DYN_BYTES);

    nms_fused_kernel<<<GRIDB, NTHR, DYN_BYTES>>>(boxes, cls, det, out);
}

// round 8
// speedup vs baseline: 1.7630x; 1.0116x over previous
#include <cuda_runtime.h>
#include <cstdint>

#define N_ANCH   300000
#define N_CLS    80
#define DET_DIM  85
#define TOPK     1000
#define MAXBOX   300
#define CAP      4096
#define NMS_THR  0.4f

#define GRIDB    148
#define NTHR     1024
#define NWARPS   (GRIDB * (NTHR / 32))     // 4736
#define NCH16    (N_ANCH / 16)             // 18750 (exact)
#define DYN_BYTES (TOPK * 32 * 4)          // 128000 B (P5 sort 32K, P7 mask 125K)

// ---------------- device scratch ----------------
__device__ unsigned int       g_scores[N_ANCH];
__device__ unsigned int       g_histA[256];
__device__ unsigned int       g_histB[256];
__device__ unsigned int       g_histC[256];
__device__ int                g_cand_cnt;
__device__ unsigned long long g_cand[CAP];
__device__ int                g_topk_idx[TOPK];
__device__ float4             g_boxk[TOPK];
__device__ unsigned int       g_maskmat[32 * TOPK];   // TRANSPOSED: [colword][row]
__device__ unsigned int       g_bar_count;
__device__ unsigned int       g_bar_gen;

// ---------------- grid barrier ----------------
__device__ __forceinline__ void gbar(unsigned int base, unsigned int k, bool wait) {
    __syncthreads();
    if (threadIdx.x == 0) {
        __threadfence();
        unsigned int a = atomicAdd(&g_bar_count, 1u) + 1u;
        if (a == GRIDB) {
            g_bar_count = 0u;
            __threadfence();
            atomicExch(&g_bar_gen, base + k);
        } else if (wait) {
            const volatile unsigned int* vg = &g_bar_gen;
            while (*vg - base < k) __nanosleep(64);
            __threadfence();
        }
    }
    __syncthreads();
}

__device__ __forceinline__ void aggInc(unsigned int* sh, unsigned int bucket) {
    unsigned int am = __activemask();
    unsigned int peers = __match_any_sync(am, bucket);
    int leader = __ffs(peers) - 1;
    if ((threadIdx.x & 31) == leader) atomicAdd(&sh[bucket], __popc(peers));
}

__device__ __forceinline__ void emit(unsigned int key, unsigned int idx, unsigned int T) {
    bool p = (key >= T);
    unsigned int am = __activemask();
    unsigned int bal = __ballot_sync(am, p);
    if (p) {
        int lane = threadIdx.x & 31;
        int leader = __ffs(bal) - 1;
        int base = 0;
        if (lane == leader) base = atomicAdd(&g_cand_cnt, __popc(bal));
        base = __shfl_sync(bal, base, leader);
        int slot = base + __popc(bal & ((1u << lane) - 1u));
        if (slot < CAP)
            g_cand[slot] = ((unsigned long long)key << 32) |
                           (unsigned long long)(0xFFFFFFFFu - idx);
    }
}

__device__ __forceinline__ void resolve256(const unsigned int* gh, unsigned int kth,
                                           unsigned int* shR,
                                           unsigned int* s_dig, unsigned int* s_kth) {
    int t = threadIdx.x;
    if (t < 256) shR[t] = gh[t];
    __syncthreads();
    for (int off = 1; off < 256; off <<= 1) {
        unsigned int v = 0, u = 0;
        if (t < 256) { v = shR[t]; u = (t + off < 256) ? shR[t + off] : 0u; }
        __syncthreads();
        if (t < 256) shR[t] = v + u;
        __syncthreads();
    }
    if (t < 256) {
        unsigned int e = (t < 255) ? shR[t + 1] : 0u;
        if (e < kth && shR[t] >= kth) { *s_dig = (unsigned int)t; *s_kth = kth - e; }
    }
    __syncthreads();
}

__device__ __forceinline__ float max20(const float4* r) {
    float a0 = fmaxf(fmaxf(r[0].x, r[0].y), fmaxf(r[0].z, r[0].w));
    float a1 = fmaxf(fmaxf(r[1].x, r[1].y), fmaxf(r[1].z, r[1].w));
    float a2 = fmaxf(fmaxf(r[2].x, r[2].y), fmaxf(r[2].z, r[2].w));
    float a3 = fmaxf(fmaxf(r[3].x, r[3].y), fmaxf(r[3].z, r[3].w));
    float a4 = fmaxf(fmaxf(r[4].x, r[4].y), fmaxf(r[4].z, r[4].w));
    return fmaxf(fmaxf(fmaxf(a0, a1), fmaxf(a2, a3)), a4);
}

// ---------------- the single fused kernel ----------------
extern "C" __global__ void __launch_bounds__(NTHR, 1)
nms_fused_kernel(const float* __restrict__ boxes,
                 const float* __restrict__ cls,
                 const float* __restrict__ det,
                 float* __restrict__ out) {
    extern __shared__ unsigned char dynsmem[];
    __shared__ unsigned int shH[256];
    __shared__ unsigned int shR[256];
    __shared__ unsigned int s_d1, s_k1, s_d2, s_k2, s_d3;
    __shared__ unsigned int keepw[32], wpref[32];
    __shared__ int  s_sel[MAXBOX];
    __shared__ int  s_nkeep;
    __shared__ unsigned int s_base;

    const int t    = threadIdx.x;
    const int blk  = blockIdx.x;
    const int gtid = blk * NTHR + t;
    const int lane = t & 31;
    const int warp = t >> 5;

    if (t == 0) s_base = atomicAdd(&g_bar_gen, 0u);
    if (t < 256) shH[t] = 0u;
    __syncthreads();
    const unsigned int base = s_base;

    // ===== P1: 4-lanes-per-anchor max, 10 LDG.128 in flight, register-only reduce =====
    {
        const float4* gp = (const float4*)cls;
        const int p = lane & 3;          // quarter within anchor
        const int a = lane >> 2;         // anchor slot (0..7)
        const int gwarp = blk * 32 + warp;
        for (int chunk = gwarp; chunk < NCH16; chunk += NWARPS) {
            const size_t b0 = (size_t)chunk * (16 * 20);   // f4 units
            float4 r0[5], r1[5];
            const size_t o0 = b0 + a * 20 + p;
            const size_t o1 = o0 + 160;                    // +8 anchors
#pragma unroll
            for (int j = 0; j < 5; j++) r0[j] = __ldcs(&gp[o0 + 4 * j]);
#pragma unroll
            for (int j = 0; j < 5; j++) r1[j] = __ldcs(&gp[o1 + 4 * j]);
            float m0 = max20(r0);
            float m1 = max20(r1);
            m0 = fmaxf(m0, __shfl_xor_sync(0xFFFFFFFFu, m0, 1));
            m0 = fmaxf(m0, __shfl_xor_sync(0xFFFFFFFFu, m0, 2));
            m1 = fmaxf(m1, __shfl_xor_sync(0xFFFFFFFFu, m1, 1));
            m1 = fmaxf(m1, __shfl_xor_sync(0xFFFFFFFFu, m1, 2));
            unsigned int k0 = __float_as_uint(m0);   // scores >= 0 -> monotonic
            unsigned int k1 = __float_as_uint(m1);
            if (p == 0) {
                int A0 = chunk * 16;
                g_scores[A0 + a]     = k0;
                g_scores[A0 + 8 + a] = k1;
                aggInc(shH, k0 >> 24);
                aggInc(shH, k1 >> 24);
            }
        }
    }
    __syncthreads();
    if (t < 256 && shH[t]) atomicAdd(&g_histA[t], shH[t]);
    gbar(base, 1, true);

    // ===== P2: resolve digit 1 + hist bits[23:16] =====
    resolve256(g_histA, TOPK, shR, &s_d1, &s_k1);
    if (t < 256) shH[t] = 0u;
    __syncthreads();
    {
        unsigned int d1 = s_d1;
        if (gtid < N_ANCH / 4) {
            uint4 k = ((const uint4*)g_scores)[gtid];
            if ((k.x >> 24) == d1) aggInc(shH, (k.x >> 16) & 255u);
            if ((k.y >> 24) == d1) aggInc(shH, (k.y >> 16) & 255u);
            if ((k.z >> 24) == d1) aggInc(shH, (k.z >> 16) & 255u);
            if ((k.w >> 24) == d1) aggInc(shH, (k.w >> 16) & 255u);
        }
    }
    __syncthreads();
    if (t < 256 && shH[t]) atomicAdd(&g_histB[t], shH[t]);
    gbar(base, 2, true);

    // ===== P3: resolve digit 2 + hist bits[15:8] =====
    resolve256(g_histB, s_k1, shR, &s_d2, &s_k2);
    if (t < 256) shH[t] = 0u;
    __syncthreads();
    {
        unsigned int pre16 = (s_d1 << 8) | s_d2;
        if (gtid < N_ANCH / 4) {
            uint4 k = ((const uint4*)g_scores)[gtid];
            if ((k.x >> 16) == pre16) aggInc(shH, (k.x >> 8) & 255u);
            if ((k.y >> 16) == pre16) aggInc(shH, (k.y >> 8) & 255u);
            if ((k.z >> 16) == pre16) aggInc(shH, (k.z >> 8) & 255u);
            if ((k.w >> 16) == pre16) aggInc(shH, (k.w >> 8) & 255u);
        }
    }
    __syncthreads();
    if (t < 256 && shH[t]) atomicAdd(&g_histC[t], shH[t]);
    gbar(base, 3, true);

    // ===== P4: resolve digit 3 -> threshold; warp-aggregated compact =====
    resolve256(g_histC, s_k2, shR, &s_d3, &s_k1 /*unused*/);
    {
        unsigned int T = (s_d1 << 24) | (s_d2 << 16) | (s_d3 << 8);
        if (gtid < N_ANCH / 4) {
            uint4 k = ((const uint4*)g_scores)[gtid];
            unsigned int bi = (unsigned int)(gtid * 4);
            emit(k.x, bi, T);
            emit(k.y, bi + 1, T);
            emit(k.z, bi + 2, T);
            emit(k.w, bi + 3, T);
        }
    }
    gbar(base, 4, true);

    // ===== P5: block0 sorts candidates + gathers boxes; block1 zeroes hists =====
    if (blk == 1) {
        if (t < 256) { g_histA[t] = 0u; g_histB[t] = 0u; g_histC[t] = 0u; }
    }
    if (blk == 0) {
        unsigned long long* scand = (unsigned long long*)dynsmem;
        int cnt = g_cand_cnt;
        __syncthreads();
        if (t == 0) g_cand_cnt = 0;
        if (cnt > CAP) cnt = CAP;
        int S = (cnt <= 2048) ? 2048 : CAP;
        for (int i = t; i < S; i += NTHR)
            scand[i] = (i < cnt) ? g_cand[i] : 0ull;
        __syncthreads();
        for (int k = 2; k <= S; k <<= 1) {
            for (int j = k >> 1; j > 0; j >>= 1) {
                for (int idx = t; idx < S; idx += NTHR) {
                    int l = idx ^ j;
                    if (l > idx) {
                        bool up = ((idx & k) == 0);
                        unsigned long long a = scand[idx], b = scand[l];
                        bool sw = up ? (a < b) : (a > b);
                        if (sw) { scand[idx] = b; scand[l] = a; }
                    }
                }
                __syncthreads();
            }
        }
        if (t < TOPK) {
            unsigned long long key = scand[t];
            int idx = (int)(0xFFFFFFFFu - (unsigned int)key);
            g_topk_idx[t] = idx;
            g_boxk[t] = ((const float4*)boxes)[idx];
        }
    }
    gbar(base, 5, true);

    // ===== P6: IoU bitmask, TRANSPOSED layout [colword][row] (bit-exact fp32) =====
    if (gtid < 32 * TOPK) {
        int wj = gtid / TOPK;            // column word
        int i  = gtid - wj * TOPK;       // row
        float4 bi = g_boxk[i];
        float ai = __fmul_rn(__fsub_rn(bi.z, bi.x), __fsub_rn(bi.w, bi.y));
        unsigned int bits = 0u;
        int j0 = wj * 32;
#pragma unroll 8
        for (int tt = 0; tt < 32; tt++) {
            int j = j0 + tt;
            if (j < TOPK) {
                float4 bj = g_boxk[j];
                float aj = __fmul_rn(__fsub_rn(bj.z, bj.x), __fsub_rn(bj.w, bj.y));
                float ih = fmaxf(__fsub_rn(fminf(bi.z, bj.z), fmaxf(bi.x, bj.x)), 0.0f);
                float iw = fmaxf(__fsub_rn(fminf(bi.w, bj.w), fmaxf(bi.y, bj.y)), 0.0f);
                float inter = __fmul_rn(ih, iw);
                float denom = __fadd_rn(__fsub_rn(__fadd_rn(ai, aj), inter), 1e-8f);
                float iou = __fdiv_rn(inter, denom);
                if (iou > NMS_THR) bits |= (1u << tt);
            }
        }
        g_maskmat[gtid] = bits;          // coalesced
    }
    gbar(base, 6, blk == 0);
    if (blk != 0) return;

    // ===== P7: block0 tiled greedy keep-scan (registers) + output gather =====
    {
        unsigned int* smask = (unsigned int*)dynsmem;   // [w*TOPK + r]
        for (int i = t; i < 32 * TOPK; i += NTHR) smask[i] = g_maskmat[i];
        __syncthreads();

        if (t < 32) {   // warp 0
            for (int tile = 0; tile < 32; tile++) {
                int r = tile * 32 + lane;
                int nrows = TOPK - tile * 32; if (nrows > 32) nrows = 32;
                bool base_i = false;
                unsigned int wt_i = 0u;
                if (r < TOPK) {
                    for (int w = 0; w < tile; w++)
                        base_i |= (keepw[w] & smask[w * TOPK + r]) != 0u;
                    wt_i = smask[tile * TOPK + r];
                }
                unsigned int bases = __ballot_sync(0xFFFFFFFFu, base_i);
                unsigned int keep_tile = 0u;
#pragma unroll
                for (int rr = 0; rr < 32; rr++) {
                    unsigned int word_r = __shfl_sync(0xFFFFFFFFu, wt_i, rr);
                    bool sup = ((bases >> rr) & 1u) ||
                               ((keep_tile & word_r & ((1u << rr) - 1u)) != 0u);
                    if (!sup && rr < nrows) keep_tile |= 1u << rr;
                }
                if (lane == 0) keepw[tile] = keep_tile;
                __syncwarp();
            }
            unsigned int kw = keepw[lane];
            unsigned int pc = __popc(kw);
            unsigned int inc = pc;
            for (int off = 1; off < 32; off <<= 1) {
                unsigned int v = __shfl_up_sync(0xFFFFFFFFu, inc, off);
                if (lane >= off) inc += v;
            }
            wpref[lane] = inc - pc;
            if (lane == 31) s_nkeep = (int)inc;
        }
        __syncthreads();

        if (t < TOPK) {
            int w = t >> 5, b = t & 31;
            unsigned int kw = keepw[w];
            if ((kw >> b) & 1u) {
                int rank = (int)wpref[w] + __popc(kw & ((1u << b) - 1u));
                if (rank < MAXBOX) s_sel[rank] = g_topk_idx[t];
            }
        }
        __syncthreads();

        int nk = s_nkeep;
        if (nk > MAXBOX) nk = MAXBOX;
        for (int e = t; e < MAXBOX * DET_DIM; e += NTHR) {
            int r = e / DET_DIM;
            int c = e - r * DET_DIM;
            out[e] = (r < nk) ? det[(size_t)s_sel[r] * DET_DIM + c] : 0.0f;
        }
    }
}

// ---------------- launch: ONE kernel ----------------
extern "C" void kernel_launch(void* const* d_in, const int* in_sizes, int n_in,
                              void* d_out, int out_size) {
    const float* boxes = (const float*)d_in[0];
    const float* cls   = (const float*)d_in[1];
    const float* det   = (const float*)d_in[2];
    float* out = (float*)d_out;

    cudaFuncSetAttribute((const void*)nms_fused_kernel,
                         cudaFuncAttributeMaxDynamicSharedMemorySize, DYN_BYTES);

    nms_fused_kernel<<<GRIDB, NTHR, DYN_BYTES>>>(boxes, cls, det, out);
}